// round 14
// baseline (speedup 1.0000x reference)
#include <cuda_runtime.h>

#define NUM_LABELS 51
#define CH 16
#define SPATIAL (1 << 21)          // 32*256*256
#define NVOX (2 * SPATIAL)
#define EPSF 1e-8f

#define V 512                      // voxels per tile (8192 tiles)
#define VPT 2
#define STRIDEW 16                 // words per entry (rinv reconstructed via shfl)
#define NBLK 888                   // 148 SMs x 6 blocks
#define NTILES (NVOX / V)

// Cross-launch accumulators: zero at load; last block re-zeroes after use.
__device__ float g_sum[800];
__device__ float g_nsum[800];
__device__ float g_cnt[50];
__device__ unsigned g_done;

__global__ __launch_bounds__(256, 6) void k_main(const float* __restrict__ pred,
                                                 const int* __restrict__ gt,
                                                 float* __restrict__ out) {
    __shared__ __align__(16) float s_buf[V * STRIDEW];   // 32 KB (reused by finalize)
    __shared__ int s_hist[NUM_LABELS];
    __shared__ int s_base[NUM_LABELS];
    __shared__ int s_last;

    const int tid  = threadIdx.x;
    const int lane = tid & 31;
    const unsigned cmask = 0xFu << (lane & 28);
    const int g = tid & 3;

    float4 aS = make_float4(0.f, 0.f, 0.f, 0.f);
    float4 aN = make_float4(0.f, 0.f, 0.f, 0.f);
    int cntAcc = 0;

    if (tid < NUM_LABELS) s_hist[tid] = 0;
    __syncthreads();

    for (int tile = blockIdx.x; tile < NTILES; tile += NBLK) {
        int n0 = tile * V;

        // ---- B: labels + warp-aggregated ranking (leader-only atomics) ----
        int lab[VPT], rnk[VPT];
        #pragma unroll
        for (int k = 0; k < VPT; k++) {
            int n = n0 + tid + k * 256;
            int l = gt[n];
            bool valid = ((unsigned)(l - 1) <= 49u);
            int lv = valid ? l : -1;
            unsigned mask = __match_any_sync(0xffffffffu, lv);
            int leader = __ffs(mask) - 1;
            int rinw = __popc(mask & ((1u << lane) - 1u));
            int b = 0;
            if (lane == leader && valid) b = atomicAdd(&s_hist[lv], __popc(mask));
            b = __shfl_sync(0xffffffffu, b, leader);
            lab[k] = lv;
            rnk[k] = b + rinw;
        }
        __syncthreads();

        // ---- C: warp-shuffle exclusive scan over 51 bins (warp 0) ----
        if (tid < 32) {
            int a = (tid < NUM_LABELS) ? s_hist[tid] : 0;
            int b = (tid + 32 < NUM_LABELS) ? s_hist[tid + 32] : 0;
            int sa = a, sb = b;
            #pragma unroll
            for (int d = 1; d < 32; d <<= 1) {
                int t1 = __shfl_up_sync(0xffffffffu, sa, d);
                int t2 = __shfl_up_sync(0xffffffffu, sb, d);
                if (lane >= d) { sa += t1; sb += t2; }
            }
            int totA = __shfl_sync(0xffffffffu, sa, 31);
            if (tid < NUM_LABELS) s_base[tid] = sa - a;
            if (tid + 32 < NUM_LABELS) s_base[tid + 32] = totA + sb - b;
        }
        if (tid >= 32 && tid < 32 + NUM_LABELS) cntAcc += s_hist[tid - 32];
        __syncthreads();

        // ---- D: load pred -> STS label-sorted (short-lived quad staging) ----
        #pragma unroll
        for (int k = 0; k < VPT; k++) {
            if (lab[k] < 0) continue;
            int n  = n0 + tid + k * 256;
            int bb = n >> 21;
            int sp = n & (SPATIAL - 1);
            const float* src = pred + ((long)bb << 25) + sp;
            int slot = s_base[lab[k]] + rnk[k];
            int rot = slot & 3;
            float* d = s_buf + slot * STRIDEW;
            #pragma unroll
            for (int q = 0; q < 4; q++) {
                float4 t;
                t.x = src[(long)(4*q + 0) << 21];
                t.y = src[(long)(4*q + 1) << 21];
                t.z = src[(long)(4*q + 2) << 21];
                t.w = src[(long)(4*q + 3) << 21];
                *(float4*)(d + (((q + rot) & 3) << 2)) = t;
            }
        }
        int rbase = 0, rcnt = 0;
        if (tid < 200) {
            int l = (tid >> 2) + 1;
            rbase = s_base[l];
            rcnt  = s_hist[l];
        }
        __syncthreads();

        // ---- E: atomic-free reduce (rinv via 4-lane shfl); idle zero hist ----
        if (tid < 200) {
            for (int j = 0; j < rcnt; j++) {
                int slot = rbase + j;
                const float4 v4 = *(const float4*)(s_buf + slot * STRIDEW
                                                   + (((g + slot) & 3) << 2));
                float ssq = v4.x * v4.x + v4.y * v4.y + v4.z * v4.z + v4.w * v4.w;
                ssq += __shfl_xor_sync(cmask, ssq, 1);
                ssq += __shfl_xor_sync(cmask, ssq, 2);
                float ri = rsqrtf(ssq);
                aS.x += v4.x;      aS.y += v4.y;      aS.z += v4.z;      aS.w += v4.w;
                aN.x += v4.x * ri; aN.y += v4.y * ri; aN.z += v4.z * ri; aN.w += v4.w * ri;
            }
        } else if (tid - 200 < NUM_LABELS) {
            s_hist[tid - 200] = 0;
        }
        __syncthreads();
    }

    // ---- Flush to global accumulators ----
    if (tid < 200) {
        int o = (tid >> 2) * CH + 4 * g;
        atomicAdd(&g_sum[o + 0], aS.x); atomicAdd(&g_sum[o + 1], aS.y);
        atomicAdd(&g_sum[o + 2], aS.z); atomicAdd(&g_sum[o + 3], aS.w);
        atomicAdd(&g_nsum[o + 0], aN.x); atomicAdd(&g_nsum[o + 1], aN.y);
        atomicAdd(&g_nsum[o + 2], aN.z); atomicAdd(&g_nsum[o + 3], aN.w);
    }
    if (tid >= 33 && tid < 33 + 50) atomicAdd(&g_cnt[tid - 33], (float)cntAcc);

    __threadfence();
    if (tid == 0) s_last = (atomicAdd(&g_done, 1u) == NBLK - 1);
    __syncthreads();
    if (!s_last) return;

    // ================= LAST BLOCK: finalize (s_buf reused) =================
    float* s_m   = s_buf;          // 800
    float* s_ns  = s_buf + 800;    // 800
    float* s_c   = s_buf + 1600;   // 50
    float* s_in  = s_buf + 1650;   // 50
    float* s_acc = s_buf + 1700;   // 2

    __threadfence();
    if (tid < 2) s_acc[tid] = 0.f;
    for (int i = tid; i < 800; i += 256) { s_m[i] = g_sum[i]; s_ns[i] = g_nsum[i]; }
    if (tid < 50) s_c[tid] = g_cnt[tid];
    __syncthreads();

    for (int i = tid; i < 800; i += 256)
        s_m[i] = s_m[i] / fmaxf(s_c[i >> 4], 1.f);
    __syncthreads();

    if (tid < 50) {
        float n2 = 0.f;
        #pragma unroll
        for (int c = 0; c < 16; c++) { float m = s_m[tid * 16 + c]; n2 += m * m; }
        float nrm = sqrtf(n2);
        s_in[tid] = 1.f / fmaxf(nrm, EPSF);

        float dot = 0.f;
        #pragma unroll
        for (int c = 0; c < 16; c++) dot += s_m[tid * 16 + c] * s_ns[tid * 16 + c];
        float intra_l = dot / (fmaxf(nrm, 1e-30f) * fmaxf(s_c[tid], 1.f));
        atomicAdd(&s_acc[1], intra_l);
    }
    __syncthreads();

    for (int i = tid; i < 800; i += 256) s_m[i] *= s_in[i >> 4];
    __syncthreads();

    float local = 0.f;
    for (int pp = tid; pp < 1225; pp += 256) {
        int i = 0, rem = pp;
        while (rem >= 49 - i) { rem -= 49 - i; i++; }
        int j = i + 1 + rem;
        float dot = 0.f;
        #pragma unroll
        for (int c = 0; c < 16; c++) dot += s_m[i * 16 + c] * s_m[j * 16 + c];
        local += fminf(fmaxf(dot, 0.f), 1.f);
    }
    atomicAdd(&s_acc[0], local);
    __syncthreads();

    if (tid == 0) out[0] = s_acc[0] * (1.f / 1225.f) - s_acc[1] * (1.f / 50.f);

    // Reset accumulators for next launch / graph replay
    __syncthreads();
    for (int i = tid; i < 800; i += 256) { g_sum[i] = 0.f; g_nsum[i] = 0.f; }
    if (tid < 50) g_cnt[tid] = 0.f;
    if (tid == 0) g_done = 0u;
}

extern "C" void kernel_launch(void* const* d_in, const int* in_sizes, int n_in,
                              void* d_out, int out_size) {
    const float* pred = (const float*)d_in[0];
    const int* gt = (const int*)d_in[1];
    float* out = (float*)d_out;

    k_main<<<NBLK, 256>>>(pred, gt, out);
}

// round 15
// speedup vs baseline: 1.1153x; 1.1153x over previous
#include <cuda_runtime.h>

#define NUM_LABELS 51
#define CH 16
#define SPATIAL (1 << 21)          // 32*256*256
#define NVOX (2 * SPATIAL)
#define EPSF 1e-8f

#define V 512                      // voxels per tile (8192 tiles)
#define VPT 2
#define STRIDEW 20                 // 16 channels + rinv + pad (R9-proven layout)
#define NBLK 740                   // 148 SMs x 5 blocks
#define NTILES (NVOX / V)

// Cross-launch accumulators: zero at load; last block re-zeroes after use.
__device__ float g_sum[800];
__device__ float g_nsum[800];
__device__ float g_cnt[50];
__device__ unsigned g_done;

__global__ __launch_bounds__(256) void k_main(const float* __restrict__ pred,
                                              const int* __restrict__ gt,
                                              float* __restrict__ out) {
    __shared__ __align__(16) float s_buf[V * STRIDEW];   // 40 KB (reused by finalize)
    __shared__ int s_hist[NUM_LABELS];
    __shared__ int s_base[NUM_LABELS];
    __shared__ int s_last;

    const int tid  = threadIdx.x;
    const int lane = tid & 31;

    float4 aS = make_float4(0.f, 0.f, 0.f, 0.f);
    float4 aN = make_float4(0.f, 0.f, 0.f, 0.f);
    int cntAcc = 0;

    if (tid < NUM_LABELS) s_hist[tid] = 0;
    __syncthreads();

    for (int tile = blockIdx.x; tile < NTILES; tile += NBLK) {
        int n0 = tile * V;

        // ---- B: labels + warp-aggregated ranking (leader-only atomics) ----
        int lab[VPT], rnk[VPT];
        #pragma unroll
        for (int k = 0; k < VPT; k++) {
            int n = n0 + tid + k * 256;
            int l = gt[n];
            bool valid = ((unsigned)(l - 1) <= 49u);
            int lv = valid ? l : -1;
            unsigned mask = __match_any_sync(0xffffffffu, lv);
            int leader = __ffs(mask) - 1;
            int rinw = __popc(mask & ((1u << lane) - 1u));
            int b = 0;
            if (lane == leader && valid) b = atomicAdd(&s_hist[lv], __popc(mask));
            b = __shfl_sync(0xffffffffu, b, leader);
            lab[k] = lv;
            rnk[k] = b + rinw;
        }
        __syncthreads();

        // ---- C: warp-shuffle exclusive scan over 51 bins (warp 0) ----
        if (tid < 32) {
            int a = (tid < NUM_LABELS) ? s_hist[tid] : 0;
            int b = (tid + 32 < NUM_LABELS) ? s_hist[tid + 32] : 0;
            int sa = a, sb = b;
            #pragma unroll
            for (int d = 1; d < 32; d <<= 1) {
                int t1 = __shfl_up_sync(0xffffffffu, sa, d);
                int t2 = __shfl_up_sync(0xffffffffu, sb, d);
                if (lane >= d) { sa += t1; sb += t2; }
            }
            int totA = __shfl_sync(0xffffffffu, sa, 31);
            if (tid < NUM_LABELS) s_base[tid] = sa - a;
            if (tid + 32 < NUM_LABELS) s_base[tid + 32] = totA + sb - b;
        }
        if (tid >= 32 && tid < 32 + NUM_LABELS) cntAcc += s_hist[tid - 32];
        __syncthreads();

        // ---- D: load pred, compute rinv, store label-sorted to shared ----
        #pragma unroll
        for (int k = 0; k < VPT; k++) {
            if (lab[k] < 0) continue;
            int n  = n0 + tid + k * 256;
            int bb = n >> 21;
            int sp = n & (SPATIAL - 1);
            const float* basep = pred + ((long)bb << 25) + sp;

            float v[CH];
            float ss = 0.f;
            #pragma unroll
            for (int c = 0; c < CH; c++) {
                v[c] = basep[(long)c << 21];     // coalesced per channel
                ss += v[c] * v[c];
            }
            float rinv = rsqrtf(ss);

            float* d = &s_buf[(s_base[lab[k]] + rnk[k]) * STRIDEW];
            #pragma unroll
            for (int q = 0; q < 4; q++)
                *(float4*)(d + 4 * q) = make_float4(v[4*q], v[4*q+1], v[4*q+2], v[4*q+3]);
            d[16] = rinv;
        }
        int rbase = 0, rcnt = 0;
        if (tid < 200) {                  // s_base/s_hist stable since phase C
            int l = (tid >> 2) + 1;
            rbase = s_base[l];
            rcnt  = s_hist[l];
        }
        __syncthreads();

        // ---- E: atomic-free segmented reduce; idle threads re-zero hist ----
        if (tid < 200) {
            int g = tid & 3;
            int j = 0;
            for (; j + 1 < rcnt; j += 2) {
                const float* e0 = &s_buf[(rbase + j) * STRIDEW];
                const float* e1 = e0 + STRIDEW;
                float4 v0 = *(const float4*)(e0 + 4 * g);
                float4 v1 = *(const float4*)(e1 + 4 * g);
                float  r0 = e0[16];
                float  r1 = e1[16];
                aS.x += v0.x + v1.x; aS.y += v0.y + v1.y;
                aS.z += v0.z + v1.z; aS.w += v0.w + v1.w;
                aN.x += v0.x * r0 + v1.x * r1; aN.y += v0.y * r0 + v1.y * r1;
                aN.z += v0.z * r0 + v1.z * r1; aN.w += v0.w * r0 + v1.w * r1;
            }
            if (j < rcnt) {
                const float* e0 = &s_buf[(rbase + j) * STRIDEW];
                float4 v0 = *(const float4*)(e0 + 4 * g);
                float  r0 = e0[16];
                aS.x += v0.x; aS.y += v0.y; aS.z += v0.z; aS.w += v0.w;
                aN.x += v0.x * r0; aN.y += v0.y * r0; aN.z += v0.z * r0; aN.w += v0.w * r0;
            }
        } else if (tid - 200 < NUM_LABELS) {
            s_hist[tid - 200] = 0;       // ready for next tile's phase B
        }
        __syncthreads();
    }

    // ---- Flush to global accumulators ----
    if (tid < 200) {
        int g = tid & 3;
        int o = (tid >> 2) * CH + 4 * g;
        atomicAdd(&g_sum[o + 0], aS.x); atomicAdd(&g_sum[o + 1], aS.y);
        atomicAdd(&g_sum[o + 2], aS.z); atomicAdd(&g_sum[o + 3], aS.w);
        atomicAdd(&g_nsum[o + 0], aN.x); atomicAdd(&g_nsum[o + 1], aN.y);
        atomicAdd(&g_nsum[o + 2], aN.z); atomicAdd(&g_nsum[o + 3], aN.w);
    }
    if (tid >= 33 && tid < 33 + 50) atomicAdd(&g_cnt[tid - 33], (float)cntAcc);

    __threadfence();
    if (tid == 0) s_last = (atomicAdd(&g_done, 1u) == NBLK - 1);
    __syncthreads();
    if (!s_last) return;

    // ================= LAST BLOCK: finalize (s_buf reused) =================
    float* s_m   = s_buf;          // 800
    float* s_ns  = s_buf + 800;    // 800
    float* s_c   = s_buf + 1600;   // 50
    float* s_in  = s_buf + 1650;   // 50
    float* s_acc = s_buf + 1700;   // 2

    __threadfence();
    if (tid < 2) s_acc[tid] = 0.f;
    for (int i = tid; i < 800; i += 256) { s_m[i] = g_sum[i]; s_ns[i] = g_nsum[i]; }
    if (tid < 50) s_c[tid] = g_cnt[tid];
    __syncthreads();

    for (int i = tid; i < 800; i += 256)
        s_m[i] = s_m[i] / fmaxf(s_c[i >> 4], 1.f);
    __syncthreads();

    // intra_l = dot(m_l, nsum_l) / (|m_l| * count_l)
    if (tid < 50) {
        float n2 = 0.f;
        #pragma unroll
        for (int c = 0; c < 16; c++) { float m = s_m[tid * 16 + c]; n2 += m * m; }
        float nrm = sqrtf(n2);
        s_in[tid] = 1.f / fmaxf(nrm, EPSF);

        float dot = 0.f;
        #pragma unroll
        for (int c = 0; c < 16; c++) dot += s_m[tid * 16 + c] * s_ns[tid * 16 + c];
        float intra_l = dot / (fmaxf(nrm, 1e-30f) * fmaxf(s_c[tid], 1.f));
        atomicAdd(&s_acc[1], intra_l);
    }
    __syncthreads();

    for (int i = tid; i < 800; i += 256) s_m[i] *= s_in[i >> 4];
    __syncthreads();

    float local = 0.f;
    for (int pp = tid; pp < 1225; pp += 256) {
        int i = 0, rem = pp;
        while (rem >= 49 - i) { rem -= 49 - i; i++; }
        int j = i + 1 + rem;
        float dot = 0.f;
        #pragma unroll
        for (int c = 0; c < 16; c++) dot += s_m[i * 16 + c] * s_m[j * 16 + c];
        local += fminf(fmaxf(dot, 0.f), 1.f);
    }
    atomicAdd(&s_acc[0], local);
    __syncthreads();

    if (tid == 0) out[0] = s_acc[0] * (1.f / 1225.f) - s_acc[1] * (1.f / 50.f);

    // Reset accumulators for next launch / graph replay
    __syncthreads();
    for (int i = tid; i < 800; i += 256) { g_sum[i] = 0.f; g_nsum[i] = 0.f; }
    if (tid < 50) g_cnt[tid] = 0.f;
    if (tid == 0) g_done = 0u;
}

extern "C" void kernel_launch(void* const* d_in, const int* in_sizes, int n_in,
                              void* d_out, int out_size) {
    const float* pred = (const float*)d_in[0];
    const int* gt = (const int*)d_in[1];
    float* out = (float*)d_out;

    k_main<<<NBLK, 256>>>(pred, gt, out);
}